// round 3
// baseline (speedup 1.0000x reference)
#include <cuda_runtime.h>

#define U_N 200000
#define M_N 100000
#define E_N 2000000
#define HD 64
#define CN 7

// ---------------- device scratch ----------------
// d_deg_* are zero at module load and re-zeroed at the END of every
// kernel_launch invocation (tail blocks of k_classify), so k_prep's atomic
// counting always starts from zero. Deterministic across graph replays.
__device__ int d_deg_u[U_N];
__device__ int d_deg_m[M_N];
__device__ int d_off_u[U_N + 1];
__device__ int d_off_m[M_N + 1];
__device__ int d_cur_u[U_N];
__device__ int d_cur_m[M_N];
__device__ int d_nbr_u[E_N];
__device__ int d_nbr_m[E_N];
__device__ float d_xu[(size_t)U_N * HD];
__device__ float d_xm[(size_t)M_N * HD];
__device__ float d_u1[(size_t)U_N * HD];
__device__ float d_m1[(size_t)M_N * HD];
__device__ float d_u2[(size_t)U_N * HD];
__device__ float d_m2[(size_t)M_N * HD];

// index loader: int64 (x64 reference) or int32 (silent downcast)
__device__ __forceinline__ int ldidx(const void* p, int i, int f64) {
    return f64 ? (int)((const long long*)p)[i] : ((const int*)p)[i];
}
// detect width from user_node_id (= arange): int64 -> word[3] (hi of elem 1) == 0
__device__ __forceinline__ int detect64(const int* uw) { return uw[3] == 0; }

// ---------------- launch 0: user gather + movie projection + degree count ----------------
__global__ __launch_bounds__(256) void k_prep(
    const int* uw, const void* unid, const void* mnid,
    const float* ue, const float* mx, const float* W, const float* bb,
    const float* memb, const void* es, const void* ed,
    int U, int M, int F, int E, int GG, int GM, int GC) {
    __shared__ float2 sW[32 * 32];
    int f64 = detect64(uw);
    if ((int)blockIdx.x < GG) {
        int j = blockIdx.x * 256 + threadIdx.x;
        if (j < U * 16) {
            int node = j >> 4, q = j & 15;
            int uid = ldidx(unid, node, f64);
            reinterpret_cast<float4*>(d_xu)[j] =
                reinterpret_cast<const float4*>(ue)[(size_t)uid * 16 + q];
        }
    } else if ((int)blockIdx.x < GG + GM) {
        for (int idx = threadIdx.x; idx < F * 32; idx += 256) {
            int f = idx >> 5, t = idx & 31;
            sW[idx] = make_float2(W[f * HD + t], W[f * HD + t + 32]);
        }
        __syncthreads();
        int lane = threadIdx.x & 31, warp = threadIdx.x >> 5;
        int mb = blockIdx.x - GG;
        for (int m = mb * 8 + warp; m < M; m += GM * 8) {
            float mxv = (lane < F) ? mx[(size_t)m * F + lane] : 0.f;
            int mid = ldidx(mnid, m, f64);
            float acc0 = bb[lane] + memb[(size_t)mid * HD + lane];
            float acc1 = bb[lane + 32] + memb[(size_t)mid * HD + lane + 32];
            for (int f = 0; f < F; f++) {
                float v = __shfl_sync(0xffffffffu, mxv, f);
                float2 wv = sW[f * 32 + lane];
                acc0 += v * wv.x;
                acc1 += v * wv.y;
            }
            d_xm[(size_t)m * HD + lane] = acc0;
            d_xm[(size_t)m * HD + lane + 32] = acc1;
        }
    } else {
        int cb = blockIdx.x - (GG + GM);
        for (int e = cb * 256 + threadIdx.x; e < E; e += GC * 256) {
            atomicAdd(&d_deg_u[ldidx(es, e, f64)], 1);
            atomicAdd(&d_deg_m[ldidx(ed, e, f64)], 1);
        }
    }
}

// ---------------- launch 1: single-block exclusive scans (u then m) + cursor init ----------------
__device__ __forceinline__ void scan_one(int* sh, const int* deg, int* off,
                                         int* cur, int n) {
    int t = threadIdx.x;
    int chunk = (n + 1023) / 1024;
    int lo = t * chunk;
    int hi = min(lo + chunk, n);
    int s = 0;
    for (int i = lo; i < hi; i++) s += deg[i];
    sh[t] = s;
    __syncthreads();
    for (int o = 1; o < 1024; o <<= 1) {
        int a = (t >= o) ? sh[t - o] : 0;
        __syncthreads();
        sh[t] += a;
        __syncthreads();
    }
    int run = sh[t] - s;  // exclusive base for this chunk
    for (int i = lo; i < hi; i++) {
        off[i] = run;
        cur[i] = run;
        run += deg[i];
    }
    if (t == 1023) off[n] = sh[1023];
    __syncthreads();
}

__global__ __launch_bounds__(1024) void k_scan(int U, int M) {
    __shared__ int sh[1024];
    scan_one(sh, d_deg_u, d_off_u, d_cur_u, U);
    scan_one(sh, d_deg_m, d_off_m, d_cur_m, M);
}

// ---------------- launch 2: fill adjacency ----------------
__global__ void k_fill(const int* uw, const void* es, const void* ed, int n) {
    int f64 = detect64(uw);
    for (int e = blockIdx.x * blockDim.x + threadIdx.x; e < n;
         e += gridDim.x * blockDim.x) {
        int s = ldidx(es, e, f64);
        int d = ldidx(ed, e, f64);
        d_nbr_u[atomicAdd(&d_cur_u[s], 1)] = d;
        d_nbr_m[atomicAdd(&d_cur_m[d], 1)] = s;
    }
}

// ---------------- launches 3-6: fused SAGE ----------------
// out = mean_agg(xs over nbrs) @ Wl + bl + xd @ Wr  (+relu)
// warp handles 2 nodes; lane owns output cols {2l, 2l+1} of both.
__device__ __forceinline__ float2 gather_row(const float* __restrict__ xs,
                                             const int* __restrict__ nbr,
                                             int s0, int s1, int lane) {
    float a0 = 0.f, a1 = 0.f;
    for (int j = s0; j < s1; j += 32) {
        int myn = (j + lane < s1) ? nbr[j + lane] : 0;
        int cnt = min(32, s1 - j);
        int jj = 0;
        for (; jj + 8 <= cnt; jj += 8) {
            int n0 = __shfl_sync(0xffffffffu, myn, jj);
            int n1 = __shfl_sync(0xffffffffu, myn, jj + 1);
            int n2 = __shfl_sync(0xffffffffu, myn, jj + 2);
            int n3 = __shfl_sync(0xffffffffu, myn, jj + 3);
            int n4 = __shfl_sync(0xffffffffu, myn, jj + 4);
            int n5 = __shfl_sync(0xffffffffu, myn, jj + 5);
            int n6 = __shfl_sync(0xffffffffu, myn, jj + 6);
            int n7 = __shfl_sync(0xffffffffu, myn, jj + 7);
            float2 r0 = *reinterpret_cast<const float2*>(xs + (size_t)n0 * HD + 2 * lane);
            float2 r1 = *reinterpret_cast<const float2*>(xs + (size_t)n1 * HD + 2 * lane);
            float2 r2 = *reinterpret_cast<const float2*>(xs + (size_t)n2 * HD + 2 * lane);
            float2 r3 = *reinterpret_cast<const float2*>(xs + (size_t)n3 * HD + 2 * lane);
            float2 r4 = *reinterpret_cast<const float2*>(xs + (size_t)n4 * HD + 2 * lane);
            float2 r5 = *reinterpret_cast<const float2*>(xs + (size_t)n5 * HD + 2 * lane);
            float2 r6 = *reinterpret_cast<const float2*>(xs + (size_t)n6 * HD + 2 * lane);
            float2 r7 = *reinterpret_cast<const float2*>(xs + (size_t)n7 * HD + 2 * lane);
            a0 += ((r0.x + r1.x) + (r2.x + r3.x)) + ((r4.x + r5.x) + (r6.x + r7.x));
            a1 += ((r0.y + r1.y) + (r2.y + r3.y)) + ((r4.y + r5.y) + (r6.y + r7.y));
        }
        for (; jj < cnt; jj++) {
            int nn = __shfl_sync(0xffffffffu, myn, jj);
            float2 r = *reinterpret_cast<const float2*>(xs + (size_t)nn * HD + 2 * lane);
            a0 += r.x;
            a1 += r.y;
        }
    }
    float inv = 1.f / (float)max(s1 - s0, 1);
    return make_float2(a0 * inv, a1 * inv);
}

__global__ __launch_bounds__(256) void k_sage(const float* __restrict__ xs,
                                              const float* __restrict__ xd,
                                              const int* __restrict__ off,
                                              const int* __restrict__ nbr,
                                              int n_dst,
                                              const float* __restrict__ Wl,
                                              const float* __restrict__ bl,
                                              const float* __restrict__ Wr,
                                              float* __restrict__ out,
                                              int doRelu) {
    // sWl/sWr[kp*32+l] = {W[2kp][2l], W[2kp][2l+1], W[2kp+1][2l], W[2kp+1][2l+1]}
    __shared__ float4 sWl[32 * 32];
    __shared__ float4 sWr[32 * 32];
    __shared__ float sb[HD];
    __shared__ float4 sact[8][64];  // per warp: [0..31]=node A, [32..63]=node B
                                    // sact[w][k] = {agg[2k],agg[2k+1],xd[2k],xd[2k+1]}

    for (int idx = threadIdx.x; idx < 32 * 32; idx += blockDim.x) {
        int kp = idx >> 5, l = idx & 31;
        sWl[idx] = make_float4(Wl[(2 * kp) * HD + 2 * l], Wl[(2 * kp) * HD + 2 * l + 1],
                               Wl[(2 * kp + 1) * HD + 2 * l], Wl[(2 * kp + 1) * HD + 2 * l + 1]);
        sWr[idx] = make_float4(Wr[(2 * kp) * HD + 2 * l], Wr[(2 * kp) * HD + 2 * l + 1],
                               Wr[(2 * kp + 1) * HD + 2 * l], Wr[(2 * kp + 1) * HD + 2 * l + 1]);
    }
    if (threadIdx.x < HD) sb[threadIdx.x] = bl[threadIdx.x];
    __syncthreads();

    int lane = threadIdx.x & 31, warp = threadIdx.x >> 5;
    float b0 = sb[2 * lane], b1 = sb[2 * lane + 1];
    float4* actA = &sact[warp][0];
    float4* actB = &sact[warp][32];

    for (int i0 = (blockIdx.x * 8 + warp) * 2; i0 < n_dst; i0 += gridDim.x * 16) {
        int hasB = (i0 + 1 < n_dst);
        int sA0 = off[i0], sA1 = off[i0 + 1];
        float2 aggA = gather_row(xs, nbr, sA0, sA1, lane);
        float2 aggB = make_float2(0.f, 0.f);
        float2 xdB = make_float2(0.f, 0.f);
        if (hasB) {
            int sB1 = off[i0 + 2];
            aggB = gather_row(xs, nbr, sA1, sB1, lane);
            xdB = *reinterpret_cast<const float2*>(xd + (size_t)(i0 + 1) * HD + 2 * lane);
        }
        float2 xdA = *reinterpret_cast<const float2*>(xd + (size_t)i0 * HD + 2 * lane);

        actA[lane] = make_float4(aggA.x, aggA.y, xdA.x, xdA.y);
        actB[lane] = make_float4(aggB.x, aggB.y, xdB.x, xdB.y);
        __syncwarp();

        float pA0 = b0, pA1 = b1, pB0 = b0, pB1 = b1;
#pragma unroll 8
        for (int kp = 0; kp < 32; kp++) {
            float4 wl = sWl[kp * 32 + lane];
            float4 wr = sWr[kp * 32 + lane];
            float4 aA = actA[kp];  // broadcast LDS.128
            float4 aB = actB[kp];
            pA0 += aA.x * wl.x + aA.y * wl.z + aA.z * wr.x + aA.w * wr.z;
            pA1 += aA.x * wl.y + aA.y * wl.w + aA.z * wr.y + aA.w * wr.w;
            pB0 += aB.x * wl.x + aB.y * wl.z + aB.z * wr.x + aB.w * wr.z;
            pB1 += aB.x * wl.y + aB.y * wl.w + aB.z * wr.y + aB.w * wr.w;
        }
        __syncwarp();
        if (doRelu) {
            pA0 = fmaxf(pA0, 0.f); pA1 = fmaxf(pA1, 0.f);
            pB0 = fmaxf(pB0, 0.f); pB1 = fmaxf(pB1, 0.f);
        }
        *reinterpret_cast<float2*>(out + (size_t)i0 * HD + 2 * lane) = make_float2(pA0, pA1);
        if (hasB)
            *reinterpret_cast<float2*>(out + (size_t)(i0 + 1) * HD + 2 * lane) = make_float2(pB0, pB1);
    }
}

// ---------------- launch 7: edge classifier + re-zero degree scratch ----------------
__global__ __launch_bounds__(256) void k_classify(const int* uw, const void* els,
                                                  const void* eld,
                                                  const float* __restrict__ W,
                                                  const float* __restrict__ b,
                                                  float* __restrict__ out, int EL,
                                                  int U, int M, int GZ, int GC) {
    if ((int)blockIdx.x < GZ) {
        int i = blockIdx.x * 256 + threadIdx.x;
        if (i < U) d_deg_u[i] = 0;
        else if (i < U + M) d_deg_m[i - U] = 0;
        return;
    }
    int f64 = detect64(uw);
    int lane = threadIdx.x & 31, warp = threadIdx.x >> 5;
    float w0[CN], w1[CN], w2[CN], w3[CN];
#pragma unroll
    for (int c = 0; c < CN; c++) {
        w0[c] = W[(2 * lane) * CN + c];
        w1[c] = W[(2 * lane + 1) * CN + c];
        w2[c] = W[(HD + 2 * lane) * CN + c];
        w3[c] = W[(HD + 2 * lane + 1) * CN + c];
    }
    int cb = blockIdx.x - GZ;
    for (int e = cb * 8 + warp; e < EL; e += GC * 8) {
        int s = ldidx(els, e, f64);
        int d = ldidx(eld, e, f64);
        float2 fu = *reinterpret_cast<const float2*>(d_u2 + (size_t)s * HD + 2 * lane);
        float2 fm = *reinterpret_cast<const float2*>(d_m2 + (size_t)d * HD + 2 * lane);
        float acc[CN];
#pragma unroll
        for (int c = 0; c < CN; c++)
            acc[c] = fu.x * w0[c] + fu.y * w1[c] + fm.x * w2[c] + fm.y * w3[c];
#pragma unroll
        for (int o = 16; o > 0; o >>= 1) {
#pragma unroll
            for (int c = 0; c < CN; c++)
                acc[c] += __shfl_down_sync(0xffffffffu, acc[c], o);
        }
        if (lane == 0) {
#pragma unroll
            for (int c = 0; c < CN; c++) out[(size_t)e * CN + c] = acc[c] + b[c];
        }
    }
}

// ---------------- host launch ----------------
extern "C" void kernel_launch(void* const* d_in, const int* in_sizes, int n_in,
                              void* d_out, int out_size) {
    const int* uw = (const int*)d_in[0];
    const void* unid = d_in[0];
    const void* mnid = d_in[1];
    const float* movie_x = (const float*)d_in[2];
    const void* esrc = d_in[3];
    const void* edst = d_in[4];
    const void* elsrc = d_in[5];
    const void* eldst = d_in[6];
    const float* user_emb = (const float*)d_in[7];
    const float* movie_emb = (const float*)d_in[8];
    const float* w_movie = (const float*)d_in[9];
    const float* b_movie = (const float*)d_in[10];

    int U = in_sizes[0];
    int M = in_sizes[1];
    int E = in_sizes[3];
    int EL = in_sizes[5];
    int F = in_sizes[2] / M;
    (void)n_in; (void)out_size;

    void *p_off_u, *p_off_m, *p_nbr_u, *p_nbr_m;
    void *p_xu, *p_xm, *p_u1, *p_m1, *p_u2, *p_m2;
    cudaGetSymbolAddress(&p_off_u, d_off_u);
    cudaGetSymbolAddress(&p_off_m, d_off_m);
    cudaGetSymbolAddress(&p_nbr_u, d_nbr_u);
    cudaGetSymbolAddress(&p_nbr_m, d_nbr_m);
    cudaGetSymbolAddress(&p_xu, d_xu);
    cudaGetSymbolAddress(&p_xm, d_xm);
    cudaGetSymbolAddress(&p_u1, d_u1);
    cudaGetSymbolAddress(&p_m1, d_m1);
    cudaGetSymbolAddress(&p_u2, d_u2);
    cudaGetSymbolAddress(&p_m2, d_m2);

    // launch 0: prep (gather user + movie proj + degree count; deg pre-zeroed)
    int GG = (U * 16 + 255) / 256;
    int GM = 1024;
    int GC = 2048;
    k_prep<<<GG + GM + GC, 256>>>(uw, unid, mnid, user_emb, movie_x, w_movie,
                                  b_movie, movie_emb, esrc, edst,
                                  U, M, F, E, GG, GM, GC);
    // launch 1: single-block scans + cursor init
    k_scan<<<1, 1024>>>(U, M);
    // launch 2: fill adjacency
    k_fill<<<2048, 256>>>(uw, esrc, edst, E);

    const int SB = 1480;
    // launch 3 (ncu capture target): sage u1
    k_sage<<<SB, 256>>>((const float*)p_xm, (const float*)p_xu, (const int*)p_off_u,
                        (const int*)p_nbr_u, U, (const float*)d_in[14],
                        (const float*)d_in[15], (const float*)d_in[16],
                        (float*)p_u1, 1);
    // launches 4-6
    k_sage<<<SB, 256>>>((const float*)p_xu, (const float*)p_xm, (const int*)p_off_m,
                        (const int*)p_nbr_m, M, (const float*)d_in[11],
                        (const float*)d_in[12], (const float*)d_in[13],
                        (float*)p_m1, 1);
    k_sage<<<SB, 256>>>((const float*)p_m1, (const float*)p_u1, (const int*)p_off_u,
                        (const int*)p_nbr_u, U, (const float*)d_in[20],
                        (const float*)d_in[21], (const float*)d_in[22],
                        (float*)p_u2, 0);
    k_sage<<<SB, 256>>>((const float*)p_u1, (const float*)p_m1, (const int*)p_off_m,
                        (const int*)p_nbr_m, M, (const float*)d_in[17],
                        (const float*)d_in[18], (const float*)d_in[19],
                        (float*)p_m2, 0);
    // launch 7: classifier + deg re-zero for next replay
    int GZ = (U + M + 255) / 256;
    k_classify<<<GZ + 2048, 256>>>(uw, elsrc, eldst, (const float*)d_in[23],
                                   (const float*)d_in[24], (float*)d_out, EL,
                                   U, M, GZ, 2048);
}

// round 4
// speedup vs baseline: 1.5832x; 1.5832x over previous
#include <cuda_runtime.h>

#define U_N 200000
#define M_N 100000
#define E_N 2000000
#define HD 64
#define CN 7
#define NTOT (U_N + M_N)

// ---------------- device scratch (static; zero-initialized at module load) ----------------
// d_deg and d_lb_flag are re-zeroed at the END of every kernel_launch (tail
// blocks of k_classify), so every graph replay starts from a clean state.
__device__ int d_deg[NTOT];
__device__ int d_off_u[U_N + 1];
__device__ int d_off_m[M_N + 1];
__device__ int d_cur_u[U_N];
__device__ int d_cur_m[M_N];
__device__ int d_nbr_u[E_N];
__device__ int d_nbr_m[E_N];
__device__ volatile int d_lb_flag[512];
__device__ int d_lb_agg[512];
__device__ int d_lb_inc[512];
// activation buffers: [N][128] floats, row = [agg(64) | xd(64)]
__device__ float4 d_act_u1[(size_t)U_N * 32];
__device__ float4 d_act_m1[(size_t)M_N * 32];
__device__ float4 d_act_u2[(size_t)U_N * 32];
__device__ float4 d_act_m2[(size_t)M_N * 32];
// final layer-2 outputs: [N][64]
__device__ float4 d_u2o[(size_t)U_N * 16];
__device__ float4 d_m2o[(size_t)M_N * 16];

// ---------------- helpers ----------------
__device__ __forceinline__ int ldidx(const void* p, int i, int f64) {
    return f64 ? (int)((const long long*)p)[i] : ((const int*)p)[i];
}
__device__ __forceinline__ int detect64(const int* uw) { return uw[3] == 0; }

__device__ __forceinline__ unsigned long long pack2(float x, float y) {
    unsigned long long r;
    asm("mov.b64 %0, {%1, %2};" : "=l"(r) : "f"(x), "f"(y));
    return r;
}
__device__ __forceinline__ float2 unpack2(unsigned long long v) {
    float2 r;
    asm("mov.b64 {%0, %1}, %2;" : "=f"(r.x), "=f"(r.y) : "l"(v));
    return r;
}
__device__ __forceinline__ void ffma2(unsigned long long& acc, unsigned long long a,
                                      unsigned long long w) {
    asm("fma.rn.f32x2 %0, %1, %2, %0;" : "+l"(acc) : "l"(a), "l"(w));
}

// ---------------- launch 0: user gather + movie projection + degree count ----------------
__global__ __launch_bounds__(256) void k_prep(
    const int* uw, const void* unid, const void* mnid,
    const float* ue, const float* mx, const float* W, const float* bb,
    const float* memb, const void* es, const void* ed,
    int U, int M, int F, int E, int GG, int GM, int GC) {
    __shared__ float2 sW[32 * 32];
    int f64 = detect64(uw);
    if ((int)blockIdx.x < GG) {
        // x_user -> xd slot of act_u1 : act_u1[n][64+4q..]
        int j = blockIdx.x * 256 + threadIdx.x;
        if (j < U * 16) {
            int node = j >> 4, q = j & 15;
            int uid = ldidx(unid, node, f64);
            d_act_u1[(size_t)node * 32 + 16 + q] =
                reinterpret_cast<const float4*>(ue)[(size_t)uid * 16 + q];
        }
    } else if ((int)blockIdx.x < GG + GM) {
        // x_movie = movie_x @ w_movie + b + movie_emb[id] -> xd slot of act_m1
        for (int idx = threadIdx.x; idx < F * 32; idx += 256) {
            int f = idx >> 5, t = idx & 31;
            sW[idx] = make_float2(W[f * HD + t], W[f * HD + t + 32]);
        }
        __syncthreads();
        int lane = threadIdx.x & 31, warp = threadIdx.x >> 5;
        int mb = blockIdx.x - GG;
        float* actm = reinterpret_cast<float*>(d_act_m1);
        for (int m = mb * 8 + warp; m < M; m += GM * 8) {
            float mxv = (lane < F) ? mx[(size_t)m * F + lane] : 0.f;
            int mid = ldidx(mnid, m, f64);
            float acc0 = bb[lane] + memb[(size_t)mid * HD + lane];
            float acc1 = bb[lane + 32] + memb[(size_t)mid * HD + lane + 32];
            for (int f = 0; f < F; f++) {
                float v = __shfl_sync(0xffffffffu, mxv, f);
                float2 wv = sW[f * 32 + lane];
                acc0 += v * wv.x;
                acc1 += v * wv.y;
            }
            actm[(size_t)m * 128 + 64 + lane] = acc0;
            actm[(size_t)m * 128 + 96 + lane] = acc1;
        }
    } else {
        int cb = blockIdx.x - (GG + GM);
        for (int e = cb * 256 + threadIdx.x; e < E; e += GC * 256) {
            atomicAdd(&d_deg[ldidx(es, e, f64)], 1);
            atomicAdd(&d_deg[U + ldidx(ed, e, f64)], 1);
        }
    }
}

// ---------------- launch 1: decoupled-lookback scan over combined deg ----------------
__global__ __launch_bounds__(1024) void k_scan_lb(int U, int M, int E) {
    __shared__ int sh[1024];
    __shared__ int sRun;
    int n = U + M;
    int tid = threadIdx.x, bid = blockIdx.x;
    int base = bid * 4096 + tid * 4;
    int4 v = make_int4(0, 0, 0, 0);
    if (base + 3 < n)
        v = *reinterpret_cast<const int4*>(d_deg + base);
    else {
        if (base < n) v.x = d_deg[base];
        if (base + 1 < n) v.y = d_deg[base + 1];
        if (base + 2 < n) v.z = d_deg[base + 2];
    }
    int loc = v.x + v.y + v.z + v.w;
    sh[tid] = loc;
    __syncthreads();
    for (int o = 1; o < 1024; o <<= 1) {
        int a = (tid >= o) ? sh[tid - o] : 0;
        __syncthreads();
        sh[tid] += a;
        __syncthreads();
    }
    int incl = sh[tid];
    int bsum = sh[1023];
    if (tid == 0) {
        int run = 0;
        if (bid == 0) {
            d_lb_inc[0] = bsum;
            __threadfence();
            d_lb_flag[0] = 2;
        } else {
            d_lb_agg[bid] = bsum;
            __threadfence();
            d_lb_flag[bid] = 1;
            int p = bid - 1;
            while (true) {
                int f;
                while ((f = d_lb_flag[p]) == 0) {}
                __threadfence();
                if (f == 2) { run += d_lb_inc[p]; break; }
                run += d_lb_agg[p];
                p--;
            }
            d_lb_inc[bid] = run + bsum;
            __threadfence();
            d_lb_flag[bid] = 2;
        }
        sRun = run;
    }
    __syncthreads();
    int e = sRun + incl - loc;
    int vv[4] = {v.x, v.y, v.z, v.w};
#pragma unroll
    for (int w = 0; w < 4; w++) {
        int gi = base + w;
        if (gi < n) {
            if (gi < U) { d_off_u[gi] = e; d_cur_u[gi] = e; }
            else { d_off_m[gi - U] = e - E; d_cur_m[gi - U] = e - E; }
        }
        e += vv[w];
    }
    if (bid == 0 && tid == 0) { d_off_u[U] = E; d_off_m[M] = E; }
}

// ---------------- launch 2: fill adjacency ----------------
__global__ void k_fill(const int* uw, const void* es, const void* ed, int n) {
    int f64 = detect64(uw);
    for (int e = blockIdx.x * blockDim.x + threadIdx.x; e < n;
         e += gridDim.x * blockDim.x) {
        int s = ldidx(es, e, f64);
        int d = ldidx(ed, e, f64);
        d_nbr_u[atomicAdd(&d_cur_u[s], 1)] = d;
        d_nbr_m[atomicAdd(&d_cur_m[d], 1)] = s;
    }
}

// ---------------- gathers: mean-aggregate src xd rows into dst agg slots ----------------
__global__ __launch_bounds__(256) void k_gather(const float* __restrict__ src,
                                                float* __restrict__ dst,
                                                const int* __restrict__ off,
                                                const int* __restrict__ nbr,
                                                int n_dst) {
    int lane = threadIdx.x & 31, warp = threadIdx.x >> 5;
    for (int i = blockIdx.x * 8 + warp; i < n_dst; i += gridDim.x * 8) {
        int s0 = off[i], s1 = off[i + 1];
        float a0 = 0.f, a1 = 0.f;
        for (int j = s0; j < s1; j += 32) {
            int myn = (j + lane < s1) ? nbr[j + lane] : 0;
            int cnt = min(32, s1 - j);
            int jj = 0;
            for (; jj + 8 <= cnt; jj += 8) {
                int n0 = __shfl_sync(0xffffffffu, myn, jj);
                int n1 = __shfl_sync(0xffffffffu, myn, jj + 1);
                int n2 = __shfl_sync(0xffffffffu, myn, jj + 2);
                int n3 = __shfl_sync(0xffffffffu, myn, jj + 3);
                int n4 = __shfl_sync(0xffffffffu, myn, jj + 4);
                int n5 = __shfl_sync(0xffffffffu, myn, jj + 5);
                int n6 = __shfl_sync(0xffffffffu, myn, jj + 6);
                int n7 = __shfl_sync(0xffffffffu, myn, jj + 7);
                float2 r0 = *reinterpret_cast<const float2*>(src + (size_t)n0 * 128 + 2 * lane);
                float2 r1 = *reinterpret_cast<const float2*>(src + (size_t)n1 * 128 + 2 * lane);
                float2 r2 = *reinterpret_cast<const float2*>(src + (size_t)n2 * 128 + 2 * lane);
                float2 r3 = *reinterpret_cast<const float2*>(src + (size_t)n3 * 128 + 2 * lane);
                float2 r4 = *reinterpret_cast<const float2*>(src + (size_t)n4 * 128 + 2 * lane);
                float2 r5 = *reinterpret_cast<const float2*>(src + (size_t)n5 * 128 + 2 * lane);
                float2 r6 = *reinterpret_cast<const float2*>(src + (size_t)n6 * 128 + 2 * lane);
                float2 r7 = *reinterpret_cast<const float2*>(src + (size_t)n7 * 128 + 2 * lane);
                a0 += ((r0.x + r1.x) + (r2.x + r3.x)) + ((r4.x + r5.x) + (r6.x + r7.x));
                a1 += ((r0.y + r1.y) + (r2.y + r3.y)) + ((r4.y + r5.y) + (r6.y + r7.y));
            }
            for (; jj < cnt; jj++) {
                int nn = __shfl_sync(0xffffffffu, myn, jj);
                float2 r = *reinterpret_cast<const float2*>(src + (size_t)nn * 128 + 2 * lane);
                a0 += r.x;
                a1 += r.y;
            }
        }
        float inv = 1.f / (float)max(s1 - s0, 1);
        *reinterpret_cast<float2*>(dst + (size_t)i * 128 + 2 * lane) =
            make_float2(a0 * inv, a1 * inv);
    }
}

// ---------------- dense transform: out = act[N][128] @ [Wl;Wr][128][64] + bl (+relu) ----------------
// Tile: 128 nodes/block, 256 threads. Thread t: col group g=t>>6 (16 cols),
// nodes n1=t&63 and n1+64. Inner loop uses packed fma.rn.f32x2.
#define XF_SMEM (128 * 132 * 4 + 128 * 32 * 8 + 32 * 8)
__global__ __launch_bounds__(256) void k_xform(const float4* __restrict__ act,
                                               const float* __restrict__ Wl,
                                               const float* __restrict__ Wr,
                                               const float* __restrict__ bl,
                                               float* __restrict__ out, int opitch,
                                               int N, int doRelu) {
    extern __shared__ char smem[];
    float* sAct = reinterpret_cast<float*>(smem);                          // [128][132]
    unsigned long long* sW =
        reinterpret_cast<unsigned long long*>(smem + 128 * 132 * 4);       // [128][32]
    unsigned long long* sB =
        reinterpret_cast<unsigned long long*>(smem + 128 * 132 * 4 + 128 * 32 * 8);

    int t = threadIdx.x;
    int lane = t & 31, warp = t >> 5;

    // stage weights: sW[k*32+cp] = {W[k][2cp], W[k][2cp+1]}, W = [Wl;Wr]
    for (int idx = t; idx < 128 * 32; idx += 256) {
        int k = idx >> 5, cp = idx & 31;
        const float* Wg = (k < 64) ? (Wl + k * HD) : (Wr + (k - 64) * HD);
        float2 wv = *reinterpret_cast<const float2*>(Wg + 2 * cp);
        sW[idx] = pack2(wv.x, wv.y);
    }
    if (t < 32) sB[t] = pack2(bl[2 * t], bl[2 * t + 1]);

    // stage act transposed: sAct[k][n], 4x4 register transpose per thread
    int n0 = blockIdx.x * 128;
    for (int rg = warp; rg < 32; rg += 8) {
        int i0 = rg * 4;
        float4 z = make_float4(0.f, 0.f, 0.f, 0.f);
        float4 v0 = (n0 + i0 + 0 < N) ? act[(size_t)(n0 + i0 + 0) * 32 + lane] : z;
        float4 v1 = (n0 + i0 + 1 < N) ? act[(size_t)(n0 + i0 + 1) * 32 + lane] : z;
        float4 v2 = (n0 + i0 + 2 < N) ? act[(size_t)(n0 + i0 + 2) * 32 + lane] : z;
        float4 v3 = (n0 + i0 + 3 < N) ? act[(size_t)(n0 + i0 + 3) * 32 + lane] : z;
        *reinterpret_cast<float4*>(sAct + (4 * lane + 0) * 132 + i0) =
            make_float4(v0.x, v1.x, v2.x, v3.x);
        *reinterpret_cast<float4*>(sAct + (4 * lane + 1) * 132 + i0) =
            make_float4(v0.y, v1.y, v2.y, v3.y);
        *reinterpret_cast<float4*>(sAct + (4 * lane + 2) * 132 + i0) =
            make_float4(v0.z, v1.z, v2.z, v3.z);
        *reinterpret_cast<float4*>(sAct + (4 * lane + 3) * 132 + i0) =
            make_float4(v0.w, v1.w, v2.w, v3.w);
    }
    __syncthreads();

    int g = t >> 6, n1 = t & 63;
    unsigned long long acc1[8], acc2[8];
#pragma unroll
    for (int j = 0; j < 8; j++) {
        acc1[j] = sB[g * 8 + j];
        acc2[j] = acc1[j];
    }
    const unsigned long long* wbase = sW + g * 8;
#pragma unroll 2
    for (int k = 0; k < 128; k++) {
        float a1f = sAct[k * 132 + n1];
        float a2f = sAct[k * 132 + n1 + 64];
        unsigned long long a1 = pack2(a1f, a1f);
        unsigned long long a2 = pack2(a2f, a2f);
        const ulonglong2* wp = reinterpret_cast<const ulonglong2*>(wbase + (size_t)k * 32);
        ulonglong2 w0 = wp[0], w1 = wp[1], w2 = wp[2], w3 = wp[3];
        ffma2(acc1[0], a1, w0.x); ffma2(acc1[1], a1, w0.y);
        ffma2(acc1[2], a1, w1.x); ffma2(acc1[3], a1, w1.y);
        ffma2(acc1[4], a1, w2.x); ffma2(acc1[5], a1, w2.y);
        ffma2(acc1[6], a1, w3.x); ffma2(acc1[7], a1, w3.y);
        ffma2(acc2[0], a2, w0.x); ffma2(acc2[1], a2, w0.y);
        ffma2(acc2[2], a2, w1.x); ffma2(acc2[3], a2, w1.y);
        ffma2(acc2[4], a2, w2.x); ffma2(acc2[5], a2, w2.y);
        ffma2(acc2[6], a2, w3.x); ffma2(acc2[7], a2, w3.y);
    }

#pragma unroll
    for (int nd = 0; nd < 2; nd++) {
        int gn = n0 + n1 + nd * 64;
        if (gn >= N) continue;
        const unsigned long long* acc = nd ? acc2 : acc1;
#pragma unroll
        for (int j = 0; j < 4; j++) {
            float2 p = unpack2(acc[2 * j]);
            float2 q = unpack2(acc[2 * j + 1]);
            if (doRelu) {
                p.x = fmaxf(p.x, 0.f); p.y = fmaxf(p.y, 0.f);
                q.x = fmaxf(q.x, 0.f); q.y = fmaxf(q.y, 0.f);
            }
            *reinterpret_cast<float4*>(out + (size_t)gn * opitch + g * 16 + 4 * j) =
                make_float4(p.x, p.y, q.x, q.y);
        }
    }
}

// ---------------- final: edge classifier + scratch re-zero ----------------
__global__ __launch_bounds__(256) void k_classify(const int* uw, const void* els,
                                                  const void* eld,
                                                  const float* __restrict__ W,
                                                  const float* __restrict__ b,
                                                  float* __restrict__ out, int EL,
                                                  int GZ, int GC) {
    if ((int)blockIdx.x < GZ) {
        int i = blockIdx.x * 256 + threadIdx.x;
        if (i < NTOT) d_deg[i] = 0;
        else if (i < NTOT + 512) d_lb_flag[i - NTOT] = 0;
        return;
    }
    int f64 = detect64(uw);
    int lane = threadIdx.x & 31, warp = threadIdx.x >> 5;
    const float* u2 = reinterpret_cast<const float*>(d_u2o);
    const float* m2 = reinterpret_cast<const float*>(d_m2o);
    float w0[CN], w1[CN], w2[CN], w3[CN];
#pragma unroll
    for (int c = 0; c < CN; c++) {
        w0[c] = W[(2 * lane) * CN + c];
        w1[c] = W[(2 * lane + 1) * CN + c];
        w2[c] = W[(HD + 2 * lane) * CN + c];
        w3[c] = W[(HD + 2 * lane + 1) * CN + c];
    }
    int cb = blockIdx.x - GZ;
    for (int e = cb * 8 + warp; e < EL; e += GC * 8) {
        int s = ldidx(els, e, f64);
        int d = ldidx(eld, e, f64);
        float2 fu = *reinterpret_cast<const float2*>(u2 + (size_t)s * HD + 2 * lane);
        float2 fm = *reinterpret_cast<const float2*>(m2 + (size_t)d * HD + 2 * lane);
        float acc[CN];
#pragma unroll
        for (int c = 0; c < CN; c++)
            acc[c] = fu.x * w0[c] + fu.y * w1[c] + fm.x * w2[c] + fm.y * w3[c];
#pragma unroll
        for (int o = 16; o > 0; o >>= 1) {
#pragma unroll
            for (int c = 0; c < CN; c++)
                acc[c] += __shfl_down_sync(0xffffffffu, acc[c], o);
        }
        if (lane == 0) {
#pragma unroll
            for (int c = 0; c < CN; c++) out[(size_t)e * CN + c] = acc[c] + b[c];
        }
    }
}

// ---------------- host launch ----------------
extern "C" void kernel_launch(void* const* d_in, const int* in_sizes, int n_in,
                              void* d_out, int out_size) {
    const int* uw = (const int*)d_in[0];
    const void* unid = d_in[0];
    const void* mnid = d_in[1];
    const float* movie_x = (const float*)d_in[2];
    const void* esrc = d_in[3];
    const void* edst = d_in[4];
    const void* elsrc = d_in[5];
    const void* eldst = d_in[6];
    const float* user_emb = (const float*)d_in[7];
    const float* movie_emb = (const float*)d_in[8];
    const float* w_movie = (const float*)d_in[9];
    const float* b_movie = (const float*)d_in[10];

    int U = in_sizes[0];
    int M = in_sizes[1];
    int E = in_sizes[3];
    int EL = in_sizes[5];
    int F = in_sizes[2] / M;
    (void)n_in; (void)out_size;

    void *p_off_u, *p_off_m, *p_nbr_u, *p_nbr_m;
    void *p_au1, *p_am1, *p_au2, *p_am2, *p_u2o, *p_m2o;
    cudaGetSymbolAddress(&p_off_u, d_off_u);
    cudaGetSymbolAddress(&p_off_m, d_off_m);
    cudaGetSymbolAddress(&p_nbr_u, d_nbr_u);
    cudaGetSymbolAddress(&p_nbr_m, d_nbr_m);
    cudaGetSymbolAddress(&p_au1, d_act_u1);
    cudaGetSymbolAddress(&p_am1, d_act_m1);
    cudaGetSymbolAddress(&p_au2, d_act_u2);
    cudaGetSymbolAddress(&p_am2, d_act_m2);
    cudaGetSymbolAddress(&p_u2o, d_u2o);
    cudaGetSymbolAddress(&p_m2o, d_m2o);

    cudaFuncSetAttribute(k_xform, cudaFuncAttributeMaxDynamicSharedMemorySize, XF_SMEM);

    float* au1 = (float*)p_au1;
    float* am1 = (float*)p_am1;
    float* au2 = (float*)p_au2;
    float* am2 = (float*)p_am2;
    const int* off_u = (const int*)p_off_u;
    const int* off_m = (const int*)p_off_m;
    const int* nbr_u = (const int*)p_nbr_u;
    const int* nbr_m = (const int*)p_nbr_m;

    // 0: prep
    int GG = (U * 16 + 255) / 256;
    int GM = 1024;
    int GC = 2048;
    k_prep<<<GG + GM + GC, 256>>>(uw, unid, mnid, user_emb, movie_x, w_movie,
                                  b_movie, movie_emb, esrc, edst,
                                  U, M, F, E, GG, GM, GC);
    // 1: scan (decoupled lookback)
    int NB = (U + M + 4095) / 4096;
    k_scan_lb<<<NB, 1024>>>(U, M, E);
    // 2: fill
    k_fill<<<2048, 256>>>(uw, esrc, edst, E);

    const int GB = 1480;
    int XU = (U + 127) / 128, XM = (M + 127) / 128;
    // 3: gather u1 (agg of x_movie over user nbrs)  [ncu capture target]
    k_gather<<<GB, 256>>>(am1 + 64, au1, off_u, nbr_u, U);
    // 4: gather m1 (agg of x_user over movie nbrs)
    k_gather<<<GB, 256>>>(au1 + 64, am1, off_m, nbr_m, M);
    // 5: xform u1 -> act_u2 xd slot (relu)
    k_xform<<<XU, 256, XF_SMEM>>>((const float4*)p_au1, (const float*)d_in[14],
                                  (const float*)d_in[16], (const float*)d_in[15],
                                  au2 + 64, 128, U, 1);
    // 6: xform m1 -> act_m2 xd slot (relu)
    k_xform<<<XM, 256, XF_SMEM>>>((const float4*)p_am1, (const float*)d_in[11],
                                  (const float*)d_in[13], (const float*)d_in[12],
                                  am2 + 64, 128, M, 1);
    // 7: gather u2 (agg of m1 over user nbrs)
    k_gather<<<GB, 256>>>(am2 + 64, au2, off_u, nbr_u, U);
    // 8: gather m2 (agg of u1 over movie nbrs)
    k_gather<<<GB, 256>>>(au2 + 64, am2, off_m, nbr_m, M);
    // 9: xform u2 -> d_u2o (no relu)
    k_xform<<<XU, 256, XF_SMEM>>>((const float4*)p_au2, (const float*)d_in[20],
                                  (const float*)d_in[22], (const float*)d_in[21],
                                  (float*)p_u2o, 64, U, 0);
    // 10: xform m2 -> d_m2o (no relu)
    k_xform<<<XM, 256, XF_SMEM>>>((const float4*)p_am2, (const float*)d_in[17],
                                  (const float*)d_in[19], (const float*)d_in[18],
                                  (float*)p_m2o, 64, M, 0);
    // 11: classifier + scratch re-zero
    int GZ = (NTOT + 512 + 255) / 256;
    k_classify<<<GZ + 2048, 256>>>(uw, elsrc, eldst, (const float*)d_in[23],
                                   (const float*)d_in[24], (float*)d_out, EL,
                                   GZ, 2048);
}